// round 1
// baseline (speedup 1.0000x reference)
#include <cuda_runtime.h>
#include <math.h>

// Problem dims
#define Bq   2
#define Sq   2048
#define Dm   512
#define Hh   8
#define DKq  64
#define Lq   4
#define DFFq 2048
#define Vv   32000
#define ROWS (Bq*Sq)   // 4096
#define QT   128
#define KT   32

// Scratch (static device globals; no runtime allocation allowed)
__device__ float g_x[ROWS*Dm];
__device__ float g_h[ROWS*Dm];
__device__ float g_qkv[ROWS*3*Dm];
__device__ float g_att[ROWS*Dm];
__device__ float g_ff[ROWS*DFFq];

// ---------------------------------------------------------------------------
// Embedding: x = tok_emb[tok]*sqrt(D) + pe[s]
// ---------------------------------------------------------------------------
__global__ __launch_bounds__(128) void embed_kernel(
    const int* __restrict__ tokens, const float* __restrict__ emb,
    const float* __restrict__ pe, float* __restrict__ x)
{
    int r = blockIdx.x, t = threadIdx.x;
    int tok = tokens[r];
    int s = r & (Sq - 1);
    const float sc = 22.62741699796952f; // sqrt(512)
    float4 e = *(const float4*)(emb + (long long)tok * Dm + t * 4);
    float4 p = *(const float4*)(pe + (long long)s * Dm + t * 4);
    float4 o;
    o.x = e.x * sc + p.x; o.y = e.y * sc + p.y;
    o.z = e.z * sc + p.z; o.w = e.w * sc + p.w;
    *(float4*)(x + (long long)r * Dm + t * 4) = o;
}

// ---------------------------------------------------------------------------
// LayerNorm over D=512, one row per 128-thread block (4 elems/thread)
// ---------------------------------------------------------------------------
__global__ __launch_bounds__(128) void ln_kernel(
    const float* __restrict__ x, const float* __restrict__ sc,
    const float* __restrict__ bi, float* __restrict__ out)
{
    int r = blockIdx.x, t = threadIdx.x;
    float4 v = *(const float4*)(x + (long long)r * Dm + t * 4);
    float sum = v.x + v.y + v.z + v.w;
    float sq  = v.x*v.x + v.y*v.y + v.z*v.z + v.w*v.w;
    #pragma unroll
    for (int o = 16; o > 0; o >>= 1) {
        sum += __shfl_xor_sync(0xffffffffu, sum, o);
        sq  += __shfl_xor_sync(0xffffffffu, sq,  o);
    }
    __shared__ float wsum[4], wsq[4];
    if ((t & 31) == 0) { wsum[t >> 5] = sum; wsq[t >> 5] = sq; }
    __syncthreads();
    float tot   = wsum[0] + wsum[1] + wsum[2] + wsum[3];
    float totsq = wsq[0]  + wsq[1]  + wsq[2]  + wsq[3];
    float mu  = tot * (1.0f / Dm);
    float var = totsq * (1.0f / Dm) - mu * mu;
    float rs  = rsqrtf(var + 1e-5f);
    float4 s4 = *(const float4*)(sc + t * 4);
    float4 b4 = *(const float4*)(bi + t * 4);
    float4 o4;
    o4.x = (v.x - mu) * rs * s4.x + b4.x;
    o4.y = (v.y - mu) * rs * s4.y + b4.y;
    o4.z = (v.z - mu) * rs * s4.z + b4.z;
    o4.w = (v.w - mu) * rs * s4.w + b4.w;
    *(float4*)(out + (long long)r * Dm + t * 4) = o4;
}

// ---------------------------------------------------------------------------
// SGEMM: C[M,N] = A[M,K] @ W[K,N] + bias[N]  (mode 0)
//        mode 1: += res[M,N] (residual, may alias C)
//        mode 2: exact GELU applied
// BM=BN=64, BK=16, 256 threads, 4x4 microtile. All dims divisible (no bounds).
// ---------------------------------------------------------------------------
__global__ __launch_bounds__(256) void sgemm_kernel(
    const float* __restrict__ A, const float* __restrict__ W,
    const float* __restrict__ bias, const float* __restrict__ res,
    float* __restrict__ C, int M, int N, int K, int mode)
{
    __shared__ float As[16][68];
    __shared__ float Bs[16][68];
    int tid = threadIdx.x;
    int rowBase = blockIdx.y * 64;
    int colBase = blockIdx.x * 64;
    int tx = tid & 15, ty = tid >> 4;
    int arow = tid >> 2,  acol = (tid & 3) * 4;
    int brow = tid >> 4,  bcol = (tid & 15) * 4;
    const float* Aptr = A + (long long)(rowBase + arow) * K + acol;
    const float* Wptr = W + (long long)brow * N + colBase + bcol;
    float acc[4][4] = {};
    for (int k0 = 0; k0 < K; k0 += 16) {
        float4 av = *(const float4*)(Aptr + k0);
        float4 wv = *(const float4*)(Wptr + (long long)k0 * N);
        As[acol + 0][arow] = av.x;
        As[acol + 1][arow] = av.y;
        As[acol + 2][arow] = av.z;
        As[acol + 3][arow] = av.w;
        *(float4*)&Bs[brow][bcol] = wv;
        __syncthreads();
        #pragma unroll
        for (int k = 0; k < 16; k++) {
            float4 a = *(const float4*)&As[k][ty * 4];
            float4 b = *(const float4*)&Bs[k][tx * 4];
            acc[0][0] += a.x*b.x; acc[0][1] += a.x*b.y; acc[0][2] += a.x*b.z; acc[0][3] += a.x*b.w;
            acc[1][0] += a.y*b.x; acc[1][1] += a.y*b.y; acc[1][2] += a.y*b.z; acc[1][3] += a.y*b.w;
            acc[2][0] += a.z*b.x; acc[2][1] += a.z*b.y; acc[2][2] += a.z*b.z; acc[2][3] += a.z*b.w;
            acc[3][0] += a.w*b.x; acc[3][1] += a.w*b.y; acc[3][2] += a.w*b.z; acc[3][3] += a.w*b.w;
        }
        __syncthreads();
    }
    int col = colBase + tx * 4;
    float4 b4 = *(const float4*)(bias + col);
    #pragma unroll
    for (int i = 0; i < 4; i++) {
        int row = rowBase + ty * 4 + i;
        float4 v;
        v.x = acc[i][0] + b4.x; v.y = acc[i][1] + b4.y;
        v.z = acc[i][2] + b4.z; v.w = acc[i][3] + b4.w;
        if (mode == 1) {
            float4 r4 = *(const float4*)(res + (long long)row * N + col);
            v.x += r4.x; v.y += r4.y; v.z += r4.z; v.w += r4.w;
        } else if (mode == 2) {
            const float k = 0.7071067811865475f;
            v.x = 0.5f * v.x * (1.0f + erff(v.x * k));
            v.y = 0.5f * v.y * (1.0f + erff(v.y * k));
            v.z = 0.5f * v.z * (1.0f + erff(v.z * k));
            v.w = 0.5f * v.w * (1.0f + erff(v.w * k));
        }
        *(float4*)(C + (long long)row * N + col) = v;
    }
}

// ---------------------------------------------------------------------------
// Causal flash attention, fp32. Grid (S/QT, H, B), 128 threads.
// One thread owns one query row: q[64] + acc[64] in registers,
// K/V tiles of 32 rows staged in smem, online softmax in 16-chunks.
// qkv layout per row of 1536: [Q(h*64..) | K(512+h*64..) | V(1024+h*64..)]
// ---------------------------------------------------------------------------
__global__ __launch_bounds__(128, 1) void attn_kernel(
    const float* __restrict__ qkv, float* __restrict__ out)
{
    __shared__ float sm[QT * 68]; // Q staging (stride 68); reused as K[0..2047] V[2048..4095]
    int tid = threadIdx.x;
    int qBase = blockIdx.x * QT;
    int h = blockIdx.y;
    int b = blockIdx.z;
    const float* base = qkv + (long long)b * Sq * (3 * Dm);

    // Stage Q tile coalesced, then copy own row to registers
    for (int t = 0; t < 64; t++) {
        int idx = t * 128 + tid;
        int row = idx >> 6, d = idx & 63;
        sm[row * 68 + d] = base[(long long)(qBase + row) * (3 * Dm) + h * DKq + d];
    }
    __syncthreads();
    float q[64];
    #pragma unroll
    for (int d4 = 0; d4 < 16; d4++) {
        float4 v = *(const float4*)&sm[tid * 68 + d4 * 4];
        q[d4*4+0] = v.x; q[d4*4+1] = v.y; q[d4*4+2] = v.z; q[d4*4+3] = v.w;
    }
    __syncthreads();

    float acc[64] = {};
    float mval = -1e30f, lval = 0.0f;
    int qi = qBase + tid;
    int kEnd = qBase + QT;

    for (int kb = 0; kb < kEnd; kb += KT) {
        // stage K and V tiles (32 x 64 each)
        for (int t = 0; t < 16; t++) {
            int idx = t * 128 + tid;
            int row = idx >> 6, d = idx & 63;
            long long g = (long long)(kb + row) * (3 * Dm) + Dm + h * DKq + d;
            sm[row * 64 + d]        = base[g];        // K
            sm[2048 + row * 64 + d] = base[g + Dm];   // V
        }
        __syncthreads();
        #pragma unroll
        for (int half = 0; half < 2; half++) {
            int kb2 = kb + half * 16;
            if (kb2 <= qi) {
                float s[16];
                #pragma unroll
                for (int j = 0; j < 16; j++) {
                    const float* kr = &sm[(half * 16 + j) * 64];
                    float d0 = 0.f;
                    #pragma unroll
                    for (int d4 = 0; d4 < 16; d4++) {
                        float4 kv = *(const float4*)&kr[d4 * 4];
                        d0 += q[d4*4+0]*kv.x + q[d4*4+1]*kv.y
                            + q[d4*4+2]*kv.z + q[d4*4+3]*kv.w;
                    }
                    s[j] = (kb2 + j <= qi) ? d0 * 0.125f : -1e30f;
                }
                float mnew = mval;
                #pragma unroll
                for (int j = 0; j < 16; j++) mnew = fmaxf(mnew, s[j]);
                float corr = __expf(mval - mnew);
                mval = mnew;
                lval *= corr;
                #pragma unroll
                for (int d = 0; d < 64; d++) acc[d] *= corr;
                #pragma unroll
                for (int j = 0; j < 16; j++) {
                    float p = __expf(s[j] - mval);
                    lval += p;
                    const float* vr = &sm[2048 + (half * 16 + j) * 64];
                    #pragma unroll
                    for (int d4 = 0; d4 < 16; d4++) {
                        float4 vv = *(const float4*)&vr[d4 * 4];
                        acc[d4*4+0] += p * vv.x; acc[d4*4+1] += p * vv.y;
                        acc[d4*4+2] += p * vv.z; acc[d4*4+3] += p * vv.w;
                    }
                }
            }
        }
        __syncthreads();
    }
    float inv = 1.0f / lval;
    float* orow = out + (long long)(b * Sq + qi) * Dm + h * DKq;
    #pragma unroll
    for (int d = 0; d < 64; d++) orow[d] = acc[d] * inv;
}

// ---------------------------------------------------------------------------
extern "C" void kernel_launch(void* const* d_in, const int* in_sizes, int n_in,
                              void* d_out, int out_size)
{
    const int*   tokens  = (const int*)  d_in[0];
    const float* tok_emb = (const float*)d_in[1];
    const float* pe      = (const float*)d_in[2];
    const float* ln1_s   = (const float*)d_in[3];
    const float* ln1_b   = (const float*)d_in[4];
    const float* w_qkv   = (const float*)d_in[5];
    const float* b_qkv   = (const float*)d_in[6];
    const float* w_o     = (const float*)d_in[7];
    const float* b_o     = (const float*)d_in[8];
    const float* ln2_s   = (const float*)d_in[9];
    const float* ln2_b   = (const float*)d_in[10];
    const float* w1      = (const float*)d_in[11];
    const float* b1      = (const float*)d_in[12];
    const float* w2      = (const float*)d_in[13];
    const float* b2      = (const float*)d_in[14];
    const float* lnf_s   = (const float*)d_in[15];
    const float* lnf_b   = (const float*)d_in[16];
    const float* head_w  = (const float*)d_in[17];
    const float* head_b  = (const float*)d_in[18];
    float* out = (float*)d_out;

    float *x, *h, *qkv, *att, *ff;
    cudaGetSymbolAddress((void**)&x,   g_x);
    cudaGetSymbolAddress((void**)&h,   g_h);
    cudaGetSymbolAddress((void**)&qkv, g_qkv);
    cudaGetSymbolAddress((void**)&att, g_att);
    cudaGetSymbolAddress((void**)&ff,  g_ff);

    embed_kernel<<<ROWS, 128>>>(tokens, tok_emb, pe, x);
    for (int l = 0; l < Lq; l++) {
        ln_kernel<<<ROWS, 128>>>(x, ln1_s + l * Dm, ln1_b + l * Dm, h);
        sgemm_kernel<<<dim3(3 * Dm / 64, ROWS / 64), 256>>>(
            h, w_qkv + (long long)l * Dm * 3 * Dm, b_qkv + l * 3 * Dm,
            nullptr, qkv, ROWS, 3 * Dm, Dm, 0);
        attn_kernel<<<dim3(Sq / QT, Hh, Bq), 128>>>(qkv, att);
        sgemm_kernel<<<dim3(Dm / 64, ROWS / 64), 256>>>(
            att, w_o + (long long)l * Dm * Dm, b_o + l * Dm,
            x, x, ROWS, Dm, Dm, 1);
        ln_kernel<<<ROWS, 128>>>(x, ln2_s + l * Dm, ln2_b + l * Dm, h);
        sgemm_kernel<<<dim3(DFFq / 64, ROWS / 64), 256>>>(
            h, w1 + (long long)l * Dm * DFFq, b1 + l * DFFq,
            nullptr, ff, ROWS, DFFq, Dm, 2);
        sgemm_kernel<<<dim3(Dm / 64, ROWS / 64), 256>>>(
            ff, w2 + (long long)l * DFFq * Dm, b2 + l * Dm,
            x, x, ROWS, Dm, DFFq, 1);
    }
    ln_kernel<<<ROWS, 128>>>(x, lnf_s, lnf_b, h);
    sgemm_kernel<<<dim3(Vv / 64, ROWS / 64), 256>>>(
        h, head_w, head_b, nullptr, out, ROWS, Vv, Dm, 0);
}

// round 3
// speedup vs baseline: 1.3211x; 1.3211x over previous
#include <cuda_runtime.h>
#include <cuda_bf16.h>
#include <math.h>
#include <stdint.h>

#define Bq   2
#define Sq   2048
#define Dm   512
#define Hh   8
#define DKq  64
#define Lq   4
#define DFFq 2048
#define Vv   32000
#define ROWS (Bq*Sq)   // 4096
#define QT   128

// ---------------- scratch (device globals; no runtime alloc) ----------------
__device__ float g_x[ROWS*Dm];
__device__ float g_h[ROWS*Dm];
__device__ float g_qkv[ROWS*3*Dm];
__device__ float g_att[ROWS*Dm];
__device__ float g_ff[ROWS*DFFq];

__device__ __nv_bfloat16 g_aHi[ROWS*DFFq];
__device__ __nv_bfloat16 g_aLo[ROWS*DFFq];

__device__ __nv_bfloat16 g_qkvT_hi[Lq*3*Dm*Dm], g_qkvT_lo[Lq*3*Dm*Dm];
__device__ __nv_bfloat16 g_woT_hi [Lq*Dm*Dm],   g_woT_lo [Lq*Dm*Dm];
__device__ __nv_bfloat16 g_w1T_hi [Lq*DFFq*Dm], g_w1T_lo [Lq*DFFq*Dm];
__device__ __nv_bfloat16 g_w2T_hi [Lq*Dm*DFFq], g_w2T_lo [Lq*Dm*DFFq];
__device__ __nv_bfloat16 g_hdT_hi [(long long)Vv*Dm], g_hdT_lo[(long long)Vv*Dm];

// ---------------- helpers ----------------
__device__ __forceinline__ uint32_t smem_u32(const void* p) {
    uint32_t a;
    asm("{ .reg .u64 t; cvta.to.shared.u64 t, %1; cvt.u32.u64 %0, t; }" : "=r"(a) : "l"(p));
    return a;
}
__device__ __forceinline__ uint32_t swz(uint32_t off) { return off ^ ((off >> 3) & 0x30u); }

__device__ __forceinline__ void cpa16(uint32_t dst, const void* src) {
    asm volatile("cp.async.cg.shared.global [%0], [%1], 16;" :: "r"(dst), "l"(src));
}
#define CP_COMMIT() asm volatile("cp.async.commit_group;" ::: "memory")
#define CP_WAIT1()  asm volatile("cp.async.wait_group 1;" ::: "memory")
#define CP_WAIT0()  asm volatile("cp.async.wait_group 0;" ::: "memory")

#define LDSM4(r, a) \
    asm volatile("ldmatrix.sync.aligned.m8n8.x4.shared.b16 {%0,%1,%2,%3}, [%4];" \
        : "=r"((r)[0]), "=r"((r)[1]), "=r"((r)[2]), "=r"((r)[3]) : "r"(a))

#define MMA(d, a, b0_, b1_) \
    asm volatile("mma.sync.aligned.m16n8k16.row.col.f32.bf16.bf16.f32 " \
        "{%0,%1,%2,%3}, {%4,%5,%6,%7}, {%8,%9}, {%0,%1,%2,%3};" \
        : "+f"((d)[0]), "+f"((d)[1]), "+f"((d)[2]), "+f"((d)[3]) \
        : "r"((a)[0]), "r"((a)[1]), "r"((a)[2]), "r"((a)[3]), "r"(b0_), "r"(b1_))

// ---------------------------------------------------------------------------
// Embedding
// ---------------------------------------------------------------------------
__global__ __launch_bounds__(128) void embed_kernel(
    const int* __restrict__ tokens, const float* __restrict__ emb,
    const float* __restrict__ pe, float* __restrict__ x)
{
    int r = blockIdx.x, t = threadIdx.x;
    int tok = tokens[r];
    int s = r & (Sq - 1);
    const float sc = 22.62741699796952f;
    float4 e = *(const float4*)(emb + (long long)tok * Dm + t * 4);
    float4 p = *(const float4*)(pe + (long long)s * Dm + t * 4);
    float4 o;
    o.x = e.x * sc + p.x; o.y = e.y * sc + p.y;
    o.z = e.z * sc + p.z; o.w = e.w * sc + p.w;
    *(float4*)(x + (long long)r * Dm + t * 4) = o;
}

// ---------------------------------------------------------------------------
// LayerNorm
// ---------------------------------------------------------------------------
__global__ __launch_bounds__(128) void ln_kernel(
    const float* __restrict__ x, const float* __restrict__ sc,
    const float* __restrict__ bi, float* __restrict__ out)
{
    int r = blockIdx.x, t = threadIdx.x;
    float4 v = *(const float4*)(x + (long long)r * Dm + t * 4);
    float sum = v.x + v.y + v.z + v.w;
    float sq  = v.x*v.x + v.y*v.y + v.z*v.z + v.w*v.w;
    #pragma unroll
    for (int o = 16; o > 0; o >>= 1) {
        sum += __shfl_xor_sync(0xffffffffu, sum, o);
        sq  += __shfl_xor_sync(0xffffffffu, sq,  o);
    }
    __shared__ float wsum[4], wsq[4];
    if ((t & 31) == 0) { wsum[t >> 5] = sum; wsq[t >> 5] = sq; }
    __syncthreads();
    float tot   = wsum[0] + wsum[1] + wsum[2] + wsum[3];
    float totsq = wsq[0]  + wsq[1]  + wsq[2]  + wsq[3];
    float mu  = tot * (1.0f / Dm);
    float var = totsq * (1.0f / Dm) - mu * mu;
    float rs  = rsqrtf(var + 1e-5f);
    float4 s4 = *(const float4*)(sc + t * 4);
    float4 b4 = *(const float4*)(bi + t * 4);
    float4 o4;
    o4.x = (v.x - mu) * rs * s4.x + b4.x;
    o4.y = (v.y - mu) * rs * s4.y + b4.y;
    o4.z = (v.z - mu) * rs * s4.z + b4.z;
    o4.w = (v.w - mu) * rs * s4.w + b4.w;
    *(float4*)(out + (long long)r * Dm + t * 4) = o4;
}

// ---------------------------------------------------------------------------
// Split fp32 -> bf16 hi/lo
// ---------------------------------------------------------------------------
__global__ __launch_bounds__(256) void split_kernel(
    const float4* __restrict__ in, uint2* __restrict__ hi, uint2* __restrict__ lo)
{
    int i = blockIdx.x * 256 + threadIdx.x;
    float4 v = in[i];
    __nv_bfloat16 h0 = __float2bfloat16(v.x), h1 = __float2bfloat16(v.y);
    __nv_bfloat16 h2 = __float2bfloat16(v.z), h3 = __float2bfloat16(v.w);
    __nv_bfloat16 l0 = __float2bfloat16(v.x - __bfloat162float(h0));
    __nv_bfloat16 l1 = __float2bfloat16(v.y - __bfloat162float(h1));
    __nv_bfloat16 l2 = __float2bfloat16(v.z - __bfloat162float(h2));
    __nv_bfloat16 l3 = __float2bfloat16(v.w - __bfloat162float(h3));
    uint2 ph, pl;
    ph.x = ((uint32_t)__bfloat16_as_ushort(h1) << 16) | __bfloat16_as_ushort(h0);
    ph.y = ((uint32_t)__bfloat16_as_ushort(h3) << 16) | __bfloat16_as_ushort(h2);
    pl.x = ((uint32_t)__bfloat16_as_ushort(l1) << 16) | __bfloat16_as_ushort(l0);
    pl.y = ((uint32_t)__bfloat16_as_ushort(l3) << 16) | __bfloat16_as_ushort(l2);
    hi[i] = ph; lo[i] = pl;
}

// ---------------------------------------------------------------------------
// Weight transpose + split: W [K,N] fp32 -> hiT/loT [N,K] bf16
// ---------------------------------------------------------------------------
__global__ __launch_bounds__(256) void wsplit_kernel(
    const float* __restrict__ W, __nv_bfloat16* __restrict__ hiT,
    __nv_bfloat16* __restrict__ loT, int K, int N)
{
    __shared__ float t[32][33];
    int nb = blockIdx.x * 32, kb = blockIdx.y * 32;
    int tx = threadIdx.x & 31, ty = threadIdx.x >> 5;
    #pragma unroll
    for (int i = 0; i < 32; i += 8)
        t[ty + i][tx] = W[(long long)(kb + ty + i) * N + nb + tx];
    __syncthreads();
    #pragma unroll
    for (int i = 0; i < 32; i += 8) {
        int r = ty + i;
        float v = t[tx][r];
        __nv_bfloat16 h = __float2bfloat16(v);
        __nv_bfloat16 l = __float2bfloat16(v - __bfloat162float(h));
        long long o = (long long)(nb + r) * K + kb + tx;
        hiT[o] = h; loT[o] = l;
    }
}

// ---------------------------------------------------------------------------
// mma.sync bf16 GEMM with hi/lo split (3 MMAs per k16).
// C[4096,N] = A[4096,K] @ B^T + bias (+res | gelu).  B given [N,K] (K-major).
// BM=BN=128, BK=32, 256 threads (8 warps, 2x4), 3-stage cp.async pipeline.
// Stage layout: Ahi 0 | Alo 8K | Bhi 16K | Blo 24K, stage stride 32K.
// ---------------------------------------------------------------------------
__global__ __launch_bounds__(256, 1) void gemm_mma(
    const __nv_bfloat16* __restrict__ Ahi, const __nv_bfloat16* __restrict__ Alo,
    const __nv_bfloat16* __restrict__ Bhi, const __nv_bfloat16* __restrict__ Blo,
    const float* __restrict__ bias, const float* __restrict__ res,
    float* __restrict__ C, int N, int K, int mode)
{
    extern __shared__ __align__(1024) char smem[];
    uint32_t smemBase = smem_u32(smem);
    int tid = threadIdx.x, lane = tid & 31, wid = tid >> 5;
    int wm = wid >> 2, wn = wid & 3;
    long long rowBase = (long long)blockIdx.y * 128;
    long long colBase = (long long)blockIdx.x * 128;

    const __nv_bfloat16* a0g = Ahi + rowBase * K;
    const __nv_bfloat16* a1g = Alo + rowBase * K;
    const __nv_bfloat16* b0g = Bhi + colBase * K;
    const __nv_bfloat16* b1g = Blo + colBase * K;

    int ld_row = tid >> 2, ld_c16 = tid & 3;          // chunk idx = i*256+tid
    uint32_t off0 = swz((uint32_t)(ld_row * 64 + ld_c16 * 16));
    uint32_t off1 = swz((uint32_t)((ld_row + 64) * 64 + ld_c16 * 16));

    auto load_stage = [&](int stg, int kc) {
        uint32_t sb = smemBase + (uint32_t)stg * 32768u;
        long long g0 = (long long)ld_row * K + kc + ld_c16 * 8;
        long long g1 = (long long)(ld_row + 64) * K + kc + ld_c16 * 8;
        cpa16(sb + off0,          a0g + g0);
        cpa16(sb + off1,          a0g + g1);
        cpa16(sb + 8192 + off0,   a1g + g0);
        cpa16(sb + 8192 + off1,   a1g + g1);
        cpa16(sb + 16384 + off0,  b0g + g0);
        cpa16(sb + 16384 + off1,  b0g + g1);
        cpa16(sb + 24576 + off0,  b1g + g0);
        cpa16(sb + 24576 + off1,  b1g + g1);
        CP_COMMIT();
    };

    int NC = K >> 5;
    load_stage(0, 0);
    if (NC > 1) load_stage(1, 32);

    float acc[4][4][4] = {};
    int rl = lane & 15, cl = lane >> 4;

    for (int c = 0; c < NC; c++) {
        if (c + 1 < NC) { CP_WAIT1(); } else { CP_WAIT0(); }
        __syncthreads();
        uint32_t sb = smemBase + (uint32_t)(c % 3) * 32768u;
        #pragma unroll
        for (int hk = 0; hk < 2; hk++) {
            uint32_t ah[4][4], al[4][4], bh[2][4], bl[2][4];
            #pragma unroll
            for (int mt = 0; mt < 4; mt++) {
                uint32_t off = swz((uint32_t)((wm * 64 + mt * 16 + rl) * 64 + (hk * 2 + cl) * 16));
                LDSM4(ah[mt], sb + off);
                LDSM4(al[mt], sb + 8192 + off);
            }
            #pragma unroll
            for (int np = 0; np < 2; np++) {
                uint32_t off = swz((uint32_t)((wn * 32 + np * 16 + rl) * 64 + (hk * 2 + cl) * 16));
                LDSM4(bh[np], sb + 16384 + off);
                LDSM4(bl[np], sb + 24576 + off);
            }
            #pragma unroll
            for (int mt = 0; mt < 4; mt++)
                #pragma unroll
                for (int nt = 0; nt < 4; nt++) {
                    int np = nt >> 1, s = nt & 1;
                    MMA(acc[mt][nt], ah[mt], bh[np][s], bh[np][2 + s]);
                    MMA(acc[mt][nt], ah[mt], bl[np][s], bl[np][2 + s]);
                    MMA(acc[mt][nt], al[mt], bh[np][s], bh[np][2 + s]);
                }
        }
        __syncthreads();
        if (c + 2 < NC) load_stage((c + 2) % 3, (c + 2) * 32);
    }

    // epilogue: d0,d1 -> (row, col..col+1); d2,d3 -> (row+8, ...)
    const float kk = 0.7071067811865475f;
    #pragma unroll
    for (int mt = 0; mt < 4; mt++) {
        #pragma unroll
        for (int nt = 0; nt < 4; nt++) {
            long long row = rowBase + wm * 64 + mt * 16 + (lane >> 2);
            long long col = colBase + wn * 32 + nt * 8 + (lane & 3) * 2;
            float bx = bias[col], by = bias[col + 1];
            #pragma unroll
            for (int hh = 0; hh < 2; hh++) {
                long long rr = row + hh * 8;
                float v0 = acc[mt][nt][hh * 2 + 0] + bx;
                float v1 = acc[mt][nt][hh * 2 + 1] + by;
                if (mode == 1) {
                    float2 r2 = *(const float2*)(res + rr * N + col);
                    v0 += r2.x; v1 += r2.y;
                } else if (mode == 2) {
                    v0 = 0.5f * v0 * (1.0f + erff(v0 * kk));
                    v1 = 0.5f * v1 * (1.0f + erff(v1 * kk));
                }
                float2 o2; o2.x = v0; o2.y = v1;
                *(float2*)(C + rr * N + col) = o2;
            }
        }
    }
}

// ---------------------------------------------------------------------------
// Causal flash attention, fp32. 256 threads: lane pair per query row
// (each thread owns 32 of 64 dims). shfl_xor(1) combines dot products.
// ---------------------------------------------------------------------------
__global__ __launch_bounds__(256, 2) void attn_kernel(
    const float* __restrict__ qkv, float* __restrict__ out)
{
    __shared__ float sm[QT * 68];
    int tid = threadIdx.x;
    int row = tid >> 1, half = tid & 1;
    int qBase = blockIdx.x * QT;
    int h = blockIdx.y;
    int b = blockIdx.z;
    const float* base = qkv + (long long)b * Sq * (3 * Dm);

    for (int t = 0; t < 32; t++) {
        int idx = t * 256 + tid;
        int r = idx >> 6, d = idx & 63;
        sm[r * 68 + d] = base[(long long)(qBase + r) * (3 * Dm) + h * DKq + d];
    }
    __syncthreads();
    float q[32];
    #pragma unroll
    for (int d4 = 0; d4 < 8; d4++) {
        float4 v = *(const float4*)&sm[row * 68 + half * 32 + d4 * 4];
        q[d4*4+0] = v.x; q[d4*4+1] = v.y; q[d4*4+2] = v.z; q[d4*4+3] = v.w;
    }
    __syncthreads();

    float acc[32] = {};
    float mval = -1e30f, lval = 0.0f;
    int qi = qBase + row;
    int kEnd = qBase + QT;

    for (int kb = 0; kb < kEnd; kb += 32) {
        for (int t = 0; t < 8; t++) {
            int idx = t * 256 + tid;
            int r = idx >> 6, d = idx & 63;
            long long g = (long long)(kb + r) * (3 * Dm) + Dm + h * DKq + d;
            sm[r * 64 + d]        = base[g];
            sm[2048 + r * 64 + d] = base[g + Dm];
        }
        __syncthreads();
        #pragma unroll
        for (int hk = 0; hk < 2; hk++) {
            int kb2 = kb + hk * 16;
            if (kb2 <= qi) {
                float s[16];
                #pragma unroll
                for (int j = 0; j < 16; j++) {
                    const float* kr = &sm[(hk * 16 + j) * 64 + half * 32];
                    float d0 = 0.f;
                    #pragma unroll
                    for (int d4 = 0; d4 < 8; d4++) {
                        float4 kv = *(const float4*)&kr[d4 * 4];
                        d0 += q[d4*4+0]*kv.x + q[d4*4+1]*kv.y
                            + q[d4*4+2]*kv.z + q[d4*4+3]*kv.w;
                    }
                    d0 += __shfl_xor_sync(0xffffffffu, d0, 1);
                    s[j] = (kb2 + j <= qi) ? d0 * 0.125f : -1e30f;
                }
                float mnew = mval;
                #pragma unroll
                for (int j = 0; j < 16; j++) mnew = fmaxf(mnew, s[j]);
                float corr = __expf(mval - mnew);
                mval = mnew;
                lval *= corr;
                #pragma unroll
                for (int d = 0; d < 32; d++) acc[d] *= corr;
                #pragma unroll
                for (int j = 0; j < 16; j++) {
                    float p = __expf(s[j] - mval);
                    lval += p;
                    const float* vr = &sm[2048 + (hk * 16 + j) * 64 + half * 32];
                    #pragma unroll
                    for (int d4 = 0; d4 < 8; d4++) {
                        float4 vv = *(const float4*)&vr[d4 * 4];
                        acc[d4*4+0] += p * vv.x; acc[d4*4+1] += p * vv.y;
                        acc[d4*4+2] += p * vv.z; acc[d4*4+3] += p * vv.w;
                    }
                }
            }
        }
        __syncthreads();
    }
    float inv = 1.0f / lval;
    float* orow = out + (long long)(b * Sq + qi) * Dm + h * DKq + half * 32;
    #pragma unroll
    for (int d = 0; d < 32; d++) orow[d] = acc[d] * inv;
}

// ---------------------------------------------------------------------------
extern "C" void kernel_launch(void* const* d_in, const int* in_sizes, int n_in,
                              void* d_out, int out_size)
{
    const int*   tokens  = (const int*)  d_in[0];
    const float* tok_emb = (const float*)d_in[1];
    const float* pe      = (const float*)d_in[2];
    const float* ln1_s   = (const float*)d_in[3];
    const float* ln1_b   = (const float*)d_in[4];
    const float* w_qkv   = (const float*)d_in[5];
    const float* b_qkv   = (const float*)d_in[6];
    const float* w_o     = (const float*)d_in[7];
    const float* b_o     = (const float*)d_in[8];
    const float* ln2_s   = (const float*)d_in[9];
    const float* ln2_b   = (const float*)d_in[10];
    const float* w1      = (const float*)d_in[11];
    const float* b1      = (const float*)d_in[12];
    const float* w2      = (const float*)d_in[13];
    const float* b2      = (const float*)d_in[14];
    const float* lnf_s   = (const float*)d_in[15];
    const float* lnf_b   = (const float*)d_in[16];
    const float* head_w  = (const float*)d_in[17];
    const float* head_b  = (const float*)d_in[18];
    float* out = (float*)d_out;

    float *x, *h, *qkv, *att, *ff;
    __nv_bfloat16 *aHi, *aLo, *qkvTh, *qkvTl, *woTh, *woTl, *w1Th, *w1Tl, *w2Th, *w2Tl, *hdTh, *hdTl;
    cudaGetSymbolAddress((void**)&x,    g_x);
    cudaGetSymbolAddress((void**)&h,    g_h);
    cudaGetSymbolAddress((void**)&qkv,  g_qkv);
    cudaGetSymbolAddress((void**)&att,  g_att);
    cudaGetSymbolAddress((void**)&ff,   g_ff);
    cudaGetSymbolAddress((void**)&aHi,  g_aHi);
    cudaGetSymbolAddress((void**)&aLo,  g_aLo);
    cudaGetSymbolAddress((void**)&qkvTh, g_qkvT_hi);
    cudaGetSymbolAddress((void**)&qkvTl, g_qkvT_lo);
    cudaGetSymbolAddress((void**)&woTh,  g_woT_hi);
    cudaGetSymbolAddress((void**)&woTl,  g_woT_lo);
    cudaGetSymbolAddress((void**)&w1Th,  g_w1T_hi);
    cudaGetSymbolAddress((void**)&w1Tl,  g_w1T_lo);
    cudaGetSymbolAddress((void**)&w2Th,  g_w2T_hi);
    cudaGetSymbolAddress((void**)&w2Tl,  g_w2T_lo);
    cudaGetSymbolAddress((void**)&hdTh,  g_hdT_hi);
    cudaGetSymbolAddress((void**)&hdTl,  g_hdT_lo);

    cudaFuncSetAttribute(gemm_mma, cudaFuncAttributeMaxDynamicSharedMemorySize, 98304);
    const int SMEM = 98304;
    dim3 tb(256);

    for (int l = 0; l < Lq; l++) {
        wsplit_kernel<<<dim3(1536/32, 512/32),  tb>>>(w_qkv + (long long)l*512*1536, qkvTh + (long long)l*1536*512, qkvTl + (long long)l*1536*512, 512, 1536);
        wsplit_kernel<<<dim3(512/32,  512/32),  tb>>>(w_o   + (long long)l*512*512,  woTh  + (long long)l*512*512,  woTl  + (long long)l*512*512,  512, 512);
        wsplit_kernel<<<dim3(2048/32, 512/32),  tb>>>(w1    + (long long)l*512*2048, w1Th  + (long long)l*2048*512, w1Tl  + (long long)l*2048*512, 512, 2048);
        wsplit_kernel<<<dim3(512/32,  2048/32), tb>>>(w2    + (long long)l*2048*512, w2Th  + (long long)l*512*2048, w2Tl  + (long long)l*512*2048, 2048, 512);
    }
    wsplit_kernel<<<dim3(32000/32, 512/32), tb>>>(head_w, hdTh, hdTl, 512, 32000);

    embed_kernel<<<ROWS, 128>>>(tokens, tok_emb, pe, x);

    for (int l = 0; l < Lq; l++) {
        ln_kernel<<<ROWS, 128>>>(x, ln1_s + l * Dm, ln1_b + l * Dm, h);
        split_kernel<<<(ROWS*Dm)/1024, 256>>>((const float4*)h, (uint2*)aHi, (uint2*)aLo);
        gemm_mma<<<dim3(1536/128, 32), 256, SMEM>>>(aHi, aLo,
            qkvTh + (long long)l*1536*512, qkvTl + (long long)l*1536*512,
            b_qkv + l*1536, nullptr, qkv, 1536, 512, 0);
        attn_kernel<<<dim3(Sq/QT, Hh, Bq), 256>>>(qkv, att);
        split_kernel<<<(ROWS*Dm)/1024, 256>>>((const float4*)att, (uint2*)aHi, (uint2*)aLo);
        gemm_mma<<<dim3(512/128, 32), 256, SMEM>>>(aHi, aLo,
            woTh + (long long)l*512*512, woTl + (long long)l*512*512,
            b_o + l*512, x, x, 512, 512, 1);
        ln_kernel<<<ROWS, 128>>>(x, ln2_s + l * Dm, ln2_b + l * Dm, h);
        split_kernel<<<(ROWS*Dm)/1024, 256>>>((const float4*)h, (uint2*)aHi, (uint2*)aLo);
        gemm_mma<<<dim3(2048/128, 32), 256, SMEM>>>(aHi, aLo,
            w1Th + (long long)l*2048*512, w1Tl + (long long)l*2048*512,
            b1 + l*2048, nullptr, ff, 2048, 512, 2);
        split_kernel<<<(ROWS*DFFq)/1024, 256>>>((const float4*)ff, (uint2*)aHi, (uint2*)aLo);
        gemm_mma<<<dim3(512/128, 32), 256, SMEM>>>(aHi, aLo,
            w2Th + (long long)l*512*2048, w2Tl + (long long)l*512*2048,
            b2 + l*512, x, x, 512, 2048, 1);
    }
    ln_kernel<<<ROWS, 128>>>(x, lnf_s, lnf_b, h);
    split_kernel<<<(ROWS*Dm)/1024, 256>>>((const float4*)h, (uint2*)aHi, (uint2*)aLo);
    gemm_mma<<<dim3(32000/128, 32), 256, SMEM>>>(aHi, aLo, hdTh, hdTl,
        head_b, nullptr, out, 32000, 512, 0);
}

// round 8
// speedup vs baseline: 1.3271x; 1.0045x over previous
#include <cuda_runtime.h>
#include <cuda_bf16.h>
#include <math.h>
#include <stdint.h>

#define Bq   2
#define Sq   2048
#define Dm   512
#define Hh   8
#define DKq  64
#define Lq   4
#define DFFq 2048
#define Vv   32000
#define ROWS (Bq*Sq)   // 4096
#define QT   128

// ---------------- scratch (device globals; no runtime alloc) ----------------
__device__ float g_x[ROWS*Dm];
__device__ float g_qkv[ROWS*3*Dm];

__device__ __nv_bfloat16 g_aHi[ROWS*Dm];      // ln / attn outputs (<=512 wide)
__device__ __nv_bfloat16 g_aLo[ROWS*Dm];
__device__ __nv_bfloat16 g_bHi[ROWS*DFFq];    // FF intermediate (2048 wide)
__device__ __nv_bfloat16 g_bLo[ROWS*DFFq];

__device__ __nv_bfloat16 g_qkvT_hi[Lq*3*Dm*Dm], g_qkvT_lo[Lq*3*Dm*Dm];
__device__ __nv_bfloat16 g_woT_hi [Lq*Dm*Dm],   g_woT_lo [Lq*Dm*Dm];
__device__ __nv_bfloat16 g_w1T_hi [Lq*DFFq*Dm], g_w1T_lo [Lq*DFFq*Dm];
__device__ __nv_bfloat16 g_w2T_hi [Lq*Dm*DFFq], g_w2T_lo [Lq*Dm*DFFq];
__device__ __nv_bfloat16 g_hdT_hi [(long long)Vv*Dm], g_hdT_lo[(long long)Vv*Dm];

// ---------------- helpers ----------------
__device__ __forceinline__ uint32_t smem_u32(const void* p) {
    uint32_t a;
    asm("{ .reg .u64 t; cvta.to.shared.u64 t, %1; cvt.u32.u64 %0, t; }" : "=r"(a) : "l"(p));
    return a;
}
__device__ __forceinline__ uint32_t swz(uint32_t off) { return off ^ ((off >> 3) & 0x30u); }

__device__ __forceinline__ void cpa16(uint32_t dst, const void* src) {
    asm volatile("cp.async.cg.shared.global [%0], [%1], 16;" :: "r"(dst), "l"(src));
}
#define CP_COMMIT() asm volatile("cp.async.commit_group;" ::: "memory")
#define CP_WAIT1()  asm volatile("cp.async.wait_group 1;" ::: "memory")
#define CP_WAIT0()  asm volatile("cp.async.wait_group 0;" ::: "memory")

#define LDSM4(r, a) \
    asm volatile("ldmatrix.sync.aligned.m8n8.x4.shared.b16 {%0,%1,%2,%3}, [%4];" \
        : "=r"((r)[0]), "=r"((r)[1]), "=r"((r)[2]), "=r"((r)[3]) : "r"(a))

#define MMA(d, a, b0_, b1_) \
    asm volatile("mma.sync.aligned.m16n8k16.row.col.f32.bf16.bf16.f32 " \
        "{%0,%1,%2,%3}, {%4,%5,%6,%7}, {%8,%9}, {%0,%1,%2,%3};" \
        : "+f"((d)[0]), "+f"((d)[1]), "+f"((d)[2]), "+f"((d)[3]) \
        : "r"((a)[0]), "r"((a)[1]), "r"((a)[2]), "r"((a)[3]), "r"(b0_), "r"(b1_))

__device__ __forceinline__ uint32_t pack_hi(float a, float b) {
    return ((uint32_t)__bfloat16_as_ushort(__float2bfloat16(b)) << 16)
         |  (uint32_t)__bfloat16_as_ushort(__float2bfloat16(a));
}
__device__ __forceinline__ uint32_t pack_lo(float a, float b) {
    float ra = a - __bfloat162float(__float2bfloat16(a));
    float rb = b - __bfloat162float(__float2bfloat16(b));
    return ((uint32_t)__bfloat16_as_ushort(__float2bfloat16(rb)) << 16)
         |  (uint32_t)__bfloat16_as_ushort(__float2bfloat16(ra));
}

// ---------------------------------------------------------------------------
// Embedding
// ---------------------------------------------------------------------------
__global__ __launch_bounds__(128) void embed_kernel(
    const int* __restrict__ tokens, const float* __restrict__ emb,
    const float* __restrict__ pe, float* __restrict__ x)
{
    int r = blockIdx.x, t = threadIdx.x;
    int tok = tokens[r];
    int s = r & (Sq - 1);
    const float sc = 22.62741699796952f;
    float4 e = *(const float4*)(emb + (long long)tok * Dm + t * 4);
    float4 p = *(const float4*)(pe + (long long)s * Dm + t * 4);
    float4 o;
    o.x = e.x * sc + p.x; o.y = e.y * sc + p.y;
    o.z = e.z * sc + p.z; o.w = e.w * sc + p.w;
    *(float4*)(x + (long long)r * Dm + t * 4) = o;
}

// ---------------------------------------------------------------------------
// LayerNorm -> bf16 hi/lo directly (fused split)
// ---------------------------------------------------------------------------
__global__ __launch_bounds__(128) void ln_kernel(
    const float* __restrict__ x, const float* __restrict__ sc,
    const float* __restrict__ bi,
    __nv_bfloat16* __restrict__ hi, __nv_bfloat16* __restrict__ lo)
{
    int r = blockIdx.x, t = threadIdx.x;
    float4 v = *(const float4*)(x + (long long)r * Dm + t * 4);
    float sum = v.x + v.y + v.z + v.w;
    float sq  = v.x*v.x + v.y*v.y + v.z*v.z + v.w*v.w;
    #pragma unroll
    for (int o = 16; o > 0; o >>= 1) {
        sum += __shfl_xor_sync(0xffffffffu, sum, o);
        sq  += __shfl_xor_sync(0xffffffffu, sq,  o);
    }
    __shared__ float wsum[4], wsq[4];
    if ((t & 31) == 0) { wsum[t >> 5] = sum; wsq[t >> 5] = sq; }
    __syncthreads();
    float tot   = wsum[0] + wsum[1] + wsum[2] + wsum[3];
    float totsq = wsq[0]  + wsq[1]  + wsq[2]  + wsq[3];
    float mu  = tot * (1.0f / Dm);
    float var = totsq * (1.0f / Dm) - mu * mu;
    float rs  = rsqrtf(var + 1e-5f);
    float4 s4 = *(const float4*)(sc + t * 4);
    float4 b4 = *(const float4*)(bi + t * 4);
    float o0 = (v.x - mu) * rs * s4.x + b4.x;
    float o1 = (v.y - mu) * rs * s4.y + b4.y;
    float o2 = (v.z - mu) * rs * s4.z + b4.z;
    float o3 = (v.w - mu) * rs * s4.w + b4.w;
    uint2 ph, pl;
    ph.x = pack_hi(o0, o1); ph.y = pack_hi(o2, o3);
    pl.x = pack_lo(o0, o1); pl.y = pack_lo(o2, o3);
    *(uint2*)&hi[(long long)r * Dm + t * 4] = ph;
    *(uint2*)&lo[(long long)r * Dm + t * 4] = pl;
}

// ---------------------------------------------------------------------------
// Weight transpose + split: W [K,N] fp32 -> hiT/loT [N,K] bf16
// ---------------------------------------------------------------------------
__global__ __launch_bounds__(256) void wsplit_kernel(
    const float* __restrict__ W, __nv_bfloat16* __restrict__ hiT,
    __nv_bfloat16* __restrict__ loT, int K, int N)
{
    __shared__ float t[32][33];
    int nb = blockIdx.x * 32, kb = blockIdx.y * 32;
    int tx = threadIdx.x & 31, ty = threadIdx.x >> 5;
    #pragma unroll
    for (int i = 0; i < 32; i += 8)
        t[ty + i][tx] = W[(long long)(kb + ty + i) * N + nb + tx];
    __syncthreads();
    #pragma unroll
    for (int i = 0; i < 32; i += 8) {
        int r = ty + i;
        float v = t[tx][r];
        __nv_bfloat16 h = __float2bfloat16(v);
        __nv_bfloat16 l = __float2bfloat16(v - __bfloat162float(h));
        long long o = (long long)(nb + r) * K + kb + tx;
        hiT[o] = h; loT[o] = l;
    }
}

// ---------------------------------------------------------------------------
// mma.sync bf16 GEMM with hi/lo split (3 MMAs per k16).
// mode 0: C=f32 out + bias. mode 1: C=f32 out + bias + res.
// mode 2: GELU(out+bias) -> CHi/CLo bf16 split (distinct buffers from A!).
// ---------------------------------------------------------------------------
__global__ __launch_bounds__(256, 1) void gemm_mma(
    const __nv_bfloat16* __restrict__ Ahi, const __nv_bfloat16* __restrict__ Alo,
    const __nv_bfloat16* __restrict__ Bhi, const __nv_bfloat16* __restrict__ Blo,
    const float* __restrict__ bias, const float* __restrict__ res,
    float* __restrict__ C, __nv_bfloat16* __restrict__ CHi,
    __nv_bfloat16* __restrict__ CLo, int N, int K, int mode)
{
    extern __shared__ __align__(1024) char smem[];
    uint32_t smemBase = smem_u32(smem);
    int tid = threadIdx.x, lane = tid & 31, wid = tid >> 5;
    int wm = wid >> 2, wn = wid & 3;
    long long rowBase = (long long)blockIdx.y * 128;
    long long colBase = (long long)blockIdx.x * 128;

    const __nv_bfloat16* a0g = Ahi + rowBase * K;
    const __nv_bfloat16* a1g = Alo + rowBase * K;
    const __nv_bfloat16* b0g = Bhi + colBase * K;
    const __nv_bfloat16* b1g = Blo + colBase * K;

    int ld_row = tid >> 2, ld_c16 = tid & 3;
    uint32_t off0 = swz((uint32_t)(ld_row * 64 + ld_c16 * 16));
    uint32_t off1 = swz((uint32_t)((ld_row + 64) * 64 + ld_c16 * 16));

    auto load_stage = [&](int stg, int kc) {
        uint32_t sb = smemBase + (uint32_t)stg * 32768u;
        long long g0 = (long long)ld_row * K + kc + ld_c16 * 8;
        long long g1 = (long long)(ld_row + 64) * K + kc + ld_c16 * 8;
        cpa16(sb + off0,          a0g + g0);
        cpa16(sb + off1,          a0g + g1);
        cpa16(sb + 8192 + off0,   a1g + g0);
        cpa16(sb + 8192 + off1,   a1g + g1);
        cpa16(sb + 16384 + off0,  b0g + g0);
        cpa16(sb + 16384 + off1,  b0g + g1);
        cpa16(sb + 24576 + off0,  b1g + g0);
        cpa16(sb + 24576 + off1,  b1g + g1);
        CP_COMMIT();
    };

    int NC = K >> 5;
    load_stage(0, 0);
    if (NC > 1) load_stage(1, 32);

    float acc[4][4][4] = {};
    int rl = lane & 15, cl = lane >> 4;

    for (int c = 0; c < NC; c++) {
        if (c + 1 < NC) { CP_WAIT1(); } else { CP_WAIT0(); }
        __syncthreads();
        uint32_t sb = smemBase + (uint32_t)(c % 3) * 32768u;
        #pragma unroll
        for (int hk = 0; hk < 2; hk++) {
            uint32_t ah[4][4], al[4][4], bh[2][4], bl[2][4];
            #pragma unroll
            for (int mt = 0; mt < 4; mt++) {
                uint32_t off = swz((uint32_t)((wm * 64 + mt * 16 + rl) * 64 + (hk * 2 + cl) * 16));
                LDSM4(ah[mt], sb + off);
                LDSM4(al[mt], sb + 8192 + off);
            }
            #pragma unroll
            for (int np = 0; np < 2; np++) {
                uint32_t off = swz((uint32_t)((wn * 32 + np * 16 + rl) * 64 + (hk * 2 + cl) * 16));
                LDSM4(bh[np], sb + 16384 + off);
                LDSM4(bl[np], sb + 24576 + off);
            }
            #pragma unroll
            for (int mt = 0; mt < 4; mt++)
                #pragma unroll
                for (int nt = 0; nt < 4; nt++) {
                    int np = nt >> 1, s = nt & 1;
                    MMA(acc[mt][nt], ah[mt], bh[np][s], bh[np][2 + s]);
                    MMA(acc[mt][nt], ah[mt], bl[np][s], bl[np][2 + s]);
                    MMA(acc[mt][nt], al[mt], bh[np][s], bh[np][2 + s]);
                }
        }
        __syncthreads();
        if (c + 2 < NC) load_stage((c + 2) % 3, (c + 2) * 32);
    }

    const float kk = 0.7071067811865475f;
    #pragma unroll
    for (int mt = 0; mt < 4; mt++) {
        #pragma unroll
        for (int nt = 0; nt < 4; nt++) {
            long long row = rowBase + wm * 64 + mt * 16 + (lane >> 2);
            long long col = colBase + wn * 32 + nt * 8 + (lane & 3) * 2;
            float bx = bias[col], by = bias[col + 1];
            #pragma unroll
            for (int hh = 0; hh < 2; hh++) {
                long long rr = row + hh * 8;
                float v0 = acc[mt][nt][hh * 2 + 0] + bx;
                float v1 = acc[mt][nt][hh * 2 + 1] + by;
                if (mode == 1) {
                    float2 r2 = *(const float2*)(res + rr * N + col);
                    v0 += r2.x; v1 += r2.y;
                    float2 o2; o2.x = v0; o2.y = v1;
                    *(float2*)(C + rr * N + col) = o2;
                } else if (mode == 2) {
                    v0 = 0.5f * v0 * (1.0f + erff(v0 * kk));
                    v1 = 0.5f * v1 * (1.0f + erff(v1 * kk));
                    *(uint32_t*)&CHi[rr * N + col] = pack_hi(v0, v1);
                    *(uint32_t*)&CLo[rr * N + col] = pack_lo(v0, v1);
                } else {
                    float2 o2; o2.x = v0; o2.y = v1;
                    *(float2*)(C + rr * N + col) = o2;
                }
            }
        }
    }
}

// ---------------------------------------------------------------------------
// Causal flash attention, fp32, writes bf16 hi/lo directly (fused split).
// ---------------------------------------------------------------------------
__global__ __launch_bounds__(256, 2) void attn_kernel(
    const float* __restrict__ qkv,
    __nv_bfloat16* __restrict__ outHi, __nv_bfloat16* __restrict__ outLo)
{
    __shared__ float sm[QT * 68];
    int tid = threadIdx.x;
    int row = tid >> 1, half = tid & 1;
    int qBase = blockIdx.x * QT;
    int h = blockIdx.y;
    int b = blockIdx.z;
    const float* base = qkv + (long long)b * Sq * (3 * Dm);

    for (int t = 0; t < 32; t++) {
        int idx = t * 256 + tid;
        int r = idx >> 6, d = idx & 63;
        sm[r * 68 + d] = base[(long long)(qBase + r) * (3 * Dm) + h * DKq + d];
    }
    __syncthreads();
    float q[32];
    #pragma unroll
    for (int d4 = 0; d4 < 8; d4++) {
        float4 v = *(const float4*)&sm[row * 68 + half * 32 + d4 * 4];
        q[d4*4+0] = v.x; q[d4*4+1] = v.y; q[d4*4+2] = v.z; q[d4*4+3] = v.w;
    }
    __syncthreads();

    float acc[32] = {};
    float mval = -1e30f, lval = 0.0f;
    int qi = qBase + row;
    int kEnd = qBase + QT;

    for (int kb = 0; kb < kEnd; kb += 32) {
        for (int t = 0; t < 8; t++) {
            int idx = t * 256 + tid;
            int r = idx >> 6, d = idx & 63;
            long long g = (long long)(kb + r) * (3 * Dm) + Dm + h * DKq + d;
            sm[r * 64 + d]        = base[g];
            sm[2048 + r * 64 + d] = base[g + Dm];
        }
        __syncthreads();
        #pragma unroll
        for (int hk = 0; hk < 2; hk++) {
            int kb2 = kb + hk * 16;
            if (kb2 <= qi) {
                float s[16];
                #pragma unroll
                for (int j = 0; j < 16; j++) {
                    const float* kr = &sm[(hk * 16 + j) * 64 + half * 32];
                    float d0 = 0.f;
                    #pragma unroll
                    for (int d4 = 0; d4 < 8; d4++) {
                        float4 kv = *(const float4*)&kr[d4 * 4];
                        d0 += q[d4*4+0]*kv.x + q[d4*4+1]*kv.y
                            + q[d4*4+2]*kv.z + q[d4*4+3]*kv.w;
                    }
                    d0 += __shfl_xor_sync(0xffffffffu, d0, 1);
                    s[j] = (kb2 + j <= qi) ? d0 * 0.125f : -1e30f;
                }
                float mnew = mval;
                #pragma unroll
                for (int j = 0; j < 16; j++) mnew = fmaxf(mnew, s[j]);
                float corr = __expf(mval - mnew);
                mval = mnew;
                lval *= corr;
                #pragma unroll
                for (int d = 0; d < 32; d++) acc[d] *= corr;
                #pragma unroll
                for (int j = 0; j < 16; j++) {
                    float p = __expf(s[j] - mval);
                    lval += p;
                    const float* vr = &sm[2048 + (hk * 16 + j) * 64 + half * 32];
                    #pragma unroll
                    for (int d4 = 0; d4 < 8; d4++) {
                        float4 vv = *(const float4*)&vr[d4 * 4];
                        acc[d4*4+0] += p * vv.x; acc[d4*4+1] += p * vv.y;
                        acc[d4*4+2] += p * vv.z; acc[d4*4+3] += p * vv.w;
                    }
                }
            }
        }
        __syncthreads();
    }
    float inv = 1.0f / lval;
    long long ob = (long long)(b * Sq + qi) * Dm + h * DKq + half * 32;
    #pragma unroll
    for (int d4 = 0; d4 < 8; d4 += 2) {
        float a0 = acc[d4*4+0]*inv, a1 = acc[d4*4+1]*inv, a2 = acc[d4*4+2]*inv, a3 = acc[d4*4+3]*inv;
        float a4 = acc[d4*4+4]*inv, a5 = acc[d4*4+5]*inv, a6 = acc[d4*4+6]*inv, a7 = acc[d4*4+7]*inv;
        uint4 ph, pl;
        ph.x = pack_hi(a0, a1); ph.y = pack_hi(a2, a3); ph.z = pack_hi(a4, a5); ph.w = pack_hi(a6, a7);
        pl.x = pack_lo(a0, a1); pl.y = pack_lo(a2, a3); pl.z = pack_lo(a4, a5); pl.w = pack_lo(a6, a7);
        *(uint4*)&outHi[ob + d4 * 4] = ph;
        *(uint4*)&outLo[ob + d4 * 4] = pl;
    }
}

// ---------------------------------------------------------------------------
extern "C" void kernel_launch(void* const* d_in, const int* in_sizes, int n_in,
                              void* d_out, int out_size)
{
    const int*   tokens  = (const int*)  d_in[0];
    const float* tok_emb = (const float*)d_in[1];
    const float* pe      = (const float*)d_in[2];
    const float* ln1_s   = (const float*)d_in[3];
    const float* ln1_b   = (const float*)d_in[4];
    const float* w_qkv   = (const float*)d_in[5];
    const float* b_qkv   = (const float*)d_in[6];
    const float* w_o     = (const float*)d_in[7];
    const float* b_o     = (const float*)d_in[8];
    const float* ln2_s   = (const float*)d_in[9];
    const float* ln2_b   = (const float*)d_in[10];
    const float* w1      = (const float*)d_in[11];
    const float* b1      = (const float*)d_in[12];
    const float* w2      = (const float*)d_in[13];
    const float* b2      = (const float*)d_in[14];
    const float* lnf_s   = (const float*)d_in[15];
    const float* lnf_b   = (const float*)d_in[16];
    const float* head_w  = (const float*)d_in[17];
    const float* head_b  = (const float*)d_in[18];
    float* out = (float*)d_out;

    float *x, *qkv;
    __nv_bfloat16 *aHi, *aLo, *bHi, *bLo, *qkvTh, *qkvTl, *woTh, *woTl, *w1Th, *w1Tl, *w2Th, *w2Tl, *hdTh, *hdTl;
    cudaGetSymbolAddress((void**)&x,    g_x);
    cudaGetSymbolAddress((void**)&qkv,  g_qkv);
    cudaGetSymbolAddress((void**)&aHi,  g_aHi);
    cudaGetSymbolAddress((void**)&aLo,  g_aLo);
    cudaGetSymbolAddress((void**)&bHi,  g_bHi);
    cudaGetSymbolAddress((void**)&bLo,  g_bLo);
    cudaGetSymbolAddress((void**)&qkvTh, g_qkvT_hi);
    cudaGetSymbolAddress((void**)&qkvTl, g_qkvT_lo);
    cudaGetSymbolAddress((void**)&woTh,  g_woT_hi);
    cudaGetSymbolAddress((void**)&woTl,  g_woT_lo);
    cudaGetSymbolAddress((void**)&w1Th,  g_w1T_hi);
    cudaGetSymbolAddress((void**)&w1Tl,  g_w1T_lo);
    cudaGetSymbolAddress((void**)&w2Th,  g_w2T_hi);
    cudaGetSymbolAddress((void**)&w2Tl,  g_w2T_lo);
    cudaGetSymbolAddress((void**)&hdTh,  g_hdT_hi);
    cudaGetSymbolAddress((void**)&hdTl,  g_hdT_lo);

    cudaFuncSetAttribute(gemm_mma, cudaFuncAttributeMaxDynamicSharedMemorySize, 98304);
    const int SMEM = 98304;
    dim3 tb(256);

    // Launch order tuned so launch #6 (ncu -s 5 -c 1) is the QKV gemm_mma.
    embed_kernel<<<ROWS, 128>>>(tokens, tok_emb, pe, x);                               // 1
    wsplit_kernel<<<dim3(1536/32, 512/32), tb>>>(w_qkv, qkvTh, qkvTl, 512, 1536);      // 2 (l=0)
    ln_kernel<<<ROWS, 128>>>(x, ln1_s, ln1_b, aHi, aLo);                               // 3
    wsplit_kernel<<<dim3(512/32, 512/32),  tb>>>(w_o, woTh, woTl, 512, 512);           // 4 (l=0)
    wsplit_kernel<<<dim3(2048/32, 512/32), tb>>>(w1, w1Th, w1Tl, 512, 2048);           // 5 (l=0)

    for (int l = 0; l < Lq; l++) {
        if (l > 0) {
            wsplit_kernel<<<dim3(1536/32, 512/32), tb>>>(w_qkv + (long long)l*512*1536, qkvTh + (long long)l*1536*512, qkvTl + (long long)l*1536*512, 512, 1536);
            wsplit_kernel<<<dim3(512/32, 512/32),  tb>>>(w_o   + (long long)l*512*512,  woTh  + (long long)l*512*512,  woTl  + (long long)l*512*512,  512, 512);
            wsplit_kernel<<<dim3(2048/32, 512/32), tb>>>(w1    + (long long)l*512*2048, w1Th  + (long long)l*2048*512, w1Tl  + (long long)l*2048*512, 512, 2048);
            ln_kernel<<<ROWS, 128>>>(x, ln1_s + l * Dm, ln1_b + l * Dm, aHi, aLo);
        }
        gemm_mma<<<dim3(1536/128, 32), 256, SMEM>>>(aHi, aLo,                          // 6 = profiled
            qkvTh + (long long)l*1536*512, qkvTl + (long long)l*1536*512,
            b_qkv + l*1536, nullptr, qkv, nullptr, nullptr, 1536, 512, 0);
        attn_kernel<<<dim3(Sq/QT, Hh, Bq), 256>>>(qkv, aHi, aLo);
        wsplit_kernel<<<dim3(512/32, 2048/32), tb>>>(w2 + (long long)l*2048*512, w2Th + (long long)l*512*2048, w2Tl + (long long)l*512*2048, 2048, 512);
        gemm_mma<<<dim3(512/128, 32), 256, SMEM>>>(aHi, aLo,
            woTh + (long long)l*512*512, woTl + (long long)l*512*512,
            b_o + l*512, x, x, nullptr, nullptr, 512, 512, 1);
        ln_kernel<<<ROWS, 128>>>(x, ln2_s + l * Dm, ln2_b + l * Dm, aHi, aLo);
        gemm_mma<<<dim3(2048/128, 32), 256, SMEM>>>(aHi, aLo,
            w1Th + (long long)l*2048*512, w1Tl + (long long)l*2048*512,
            b1 + l*2048, nullptr, nullptr, bHi, bLo, 2048, 512, 2);
        gemm_mma<<<dim3(512/128, 32), 256, SMEM>>>(bHi, bLo,
            w2Th + (long long)l*512*2048, w2Tl + (long long)l*512*2048,
            b2 + l*512, x, x, nullptr, nullptr, 512, 2048, 1);
    }
    wsplit_kernel<<<dim3(32000/32, 512/32), tb>>>(head_w, hdTh, hdTl, 512, 32000);
    ln_kernel<<<ROWS, 128>>>(x, lnf_s, lnf_b, aHi, aLo);
    gemm_mma<<<dim3(32000/128, 32), 256, SMEM>>>(aHi, aLo, hdTh, hdTl,
        head_b, nullptr, out, nullptr, nullptr, 32000, 512, 0);
}

// round 9
// speedup vs baseline: 2.9348x; 2.2114x over previous
#include <cuda_runtime.h>
#include <cuda_bf16.h>
#include <math.h>
#include <stdint.h>

#define Bq   2
#define Sq   2048
#define Dm   512
#define Hh   8
#define DKq  64
#define Lq   4
#define DFFq 2048
#define Vv   32000
#define ROWS (Bq*Sq)   // 4096

// ---------------- scratch (device globals; no runtime alloc) ----------------
__device__ float g_x[ROWS*Dm];

__device__ __nv_bfloat16 g_aHi[ROWS*Dm];      // ln / attn outputs (<=512 wide)
__device__ __nv_bfloat16 g_aLo[ROWS*Dm];
__device__ __nv_bfloat16 g_bHi[ROWS*DFFq];    // qkv split (1536) / FF intermediate (2048)
__device__ __nv_bfloat16 g_bLo[ROWS*DFFq];

__device__ __nv_bfloat16 g_qkvT_hi[Lq*3*Dm*Dm], g_qkvT_lo[Lq*3*Dm*Dm];
__device__ __nv_bfloat16 g_woT_hi [Lq*Dm*Dm],   g_woT_lo [Lq*Dm*Dm];
__device__ __nv_bfloat16 g_w1T_hi [Lq*DFFq*Dm], g_w1T_lo [Lq*DFFq*Dm];
__device__ __nv_bfloat16 g_w2T_hi [Lq*Dm*DFFq], g_w2T_lo [Lq*Dm*DFFq];
__device__ __nv_bfloat16 g_hdT_hi [(long long)Vv*Dm], g_hdT_lo[(long long)Vv*Dm];

// ---------------- helpers ----------------
__device__ __forceinline__ uint32_t smem_u32(const void* p) {
    uint32_t a;
    asm("{ .reg .u64 t; cvta.to.shared.u64 t, %1; cvt.u32.u64 %0, t; }" : "=r"(a) : "l"(p));
    return a;
}
__device__ __forceinline__ uint32_t swz(uint32_t off)    { return off ^ ((off >> 3) & 0x30u); }       // 64B rows
__device__ __forceinline__ uint32_t swz128(uint32_t off) { return off ^ (((off >> 7) & 7u) << 4); }   // 128B rows

__device__ __forceinline__ void cpa16(uint32_t dst, const void* src) {
    asm volatile("cp.async.cg.shared.global [%0], [%1], 16;" :: "r"(dst), "l"(src));
}
#define CP_COMMIT() asm volatile("cp.async.commit_group;" ::: "memory")
#define CP_WAIT1()  asm volatile("cp.async.wait_group 1;" ::: "memory")
#define CP_WAIT0()  asm volatile("cp.async.wait_group 0;" ::: "memory")

#define LDSM4(r, a) \
    asm volatile("ldmatrix.sync.aligned.m8n8.x4.shared.b16 {%0,%1,%2,%3}, [%4];" \
        : "=r"((r)[0]), "=r"((r)[1]), "=r"((r)[2]), "=r"((r)[3]) : "r"(a))
#define LDSM4T(r, a) \
    asm volatile("ldmatrix.sync.aligned.m8n8.x4.trans.shared.b16 {%0,%1,%2,%3}, [%4];" \
        : "=r"((r)[0]), "=r"((r)[1]), "=r"((r)[2]), "=r"((r)[3]) : "r"(a))

#define MMA(d, a, b0_, b1_) \
    asm volatile("mma.sync.aligned.m16n8k16.row.col.f32.bf16.bf16.f32 " \
        "{%0,%1,%2,%3}, {%4,%5,%6,%7}, {%8,%9}, {%0,%1,%2,%3};" \
        : "+f"((d)[0]), "+f"((d)[1]), "+f"((d)[2]), "+f"((d)[3]) \
        : "r"((a)[0]), "r"((a)[1]), "r"((a)[2]), "r"((a)[3]), "r"(b0_), "r"(b1_))

__device__ __forceinline__ uint32_t pack_hi(float a, float b) {
    return ((uint32_t)__bfloat16_as_ushort(__float2bfloat16(b)) << 16)
         |  (uint32_t)__bfloat16_as_ushort(__float2bfloat16(a));
}
__device__ __forceinline__ uint32_t pack_lo(float a, float b) {
    float ra = a - __bfloat162float(__float2bfloat16(a));
    float rb = b - __bfloat162float(__float2bfloat16(b));
    return ((uint32_t)__bfloat16_as_ushort(__float2bfloat16(rb)) << 16)
         |  (uint32_t)__bfloat16_as_ushort(__float2bfloat16(ra));
}

// ---------------------------------------------------------------------------
// Embedding
// ---------------------------------------------------------------------------
__global__ __launch_bounds__(128) void embed_kernel(
    const int* __restrict__ tokens, const float* __restrict__ emb,
    const float* __restrict__ pe, float* __restrict__ x)
{
    int r = blockIdx.x, t = threadIdx.x;
    int tok = tokens[r];
    int s = r & (Sq - 1);
    const float sc = 22.62741699796952f;
    float4 e = *(const float4*)(emb + (long long)tok * Dm + t * 4);
    float4 p = *(const float4*)(pe + (long long)s * Dm + t * 4);
    float4 o;
    o.x = e.x * sc + p.x; o.y = e.y * sc + p.y;
    o.z = e.z * sc + p.z; o.w = e.w * sc + p.w;
    *(float4*)(x + (long long)r * Dm + t * 4) = o;
}

// ---------------------------------------------------------------------------
// LayerNorm -> bf16 hi/lo
// ---------------------------------------------------------------------------
__global__ __launch_bounds__(128) void ln_kernel(
    const float* __restrict__ x, const float* __restrict__ sc,
    const float* __restrict__ bi,
    __nv_bfloat16* __restrict__ hi, __nv_bfloat16* __restrict__ lo)
{
    int r = blockIdx.x, t = threadIdx.x;
    float4 v = *(const float4*)(x + (long long)r * Dm + t * 4);
    float sum = v.x + v.y + v.z + v.w;
    float sq  = v.x*v.x + v.y*v.y + v.z*v.z + v.w*v.w;
    #pragma unroll
    for (int o = 16; o > 0; o >>= 1) {
        sum += __shfl_xor_sync(0xffffffffu, sum, o);
        sq  += __shfl_xor_sync(0xffffffffu, sq,  o);
    }
    __shared__ float wsum[4], wsq[4];
    if ((t & 31) == 0) { wsum[t >> 5] = sum; wsq[t >> 5] = sq; }
    __syncthreads();
    float tot   = wsum[0] + wsum[1] + wsum[2] + wsum[3];
    float totsq = wsq[0]  + wsq[1]  + wsq[2]  + wsq[3];
    float mu  = tot * (1.0f / Dm);
    float var = totsq * (1.0f / Dm) - mu * mu;
    float rs  = rsqrtf(var + 1e-5f);
    float4 s4 = *(const float4*)(sc + t * 4);
    float4 b4 = *(const float4*)(bi + t * 4);
    float o0 = (v.x - mu) * rs * s4.x + b4.x;
    float o1 = (v.y - mu) * rs * s4.y + b4.y;
    float o2 = (v.z - mu) * rs * s4.z + b4.z;
    float o3 = (v.w - mu) * rs * s4.w + b4.w;
    uint2 ph, pl;
    ph.x = pack_hi(o0, o1); ph.y = pack_hi(o2, o3);
    pl.x = pack_lo(o0, o1); pl.y = pack_lo(o2, o3);
    *(uint2*)&hi[(long long)r * Dm + t * 4] = ph;
    *(uint2*)&lo[(long long)r * Dm + t * 4] = pl;
}

// ---------------------------------------------------------------------------
// Weight transpose + split: W [K,N] fp32 -> hiT/loT [N,K] bf16
// ---------------------------------------------------------------------------
__global__ __launch_bounds__(256) void wsplit_kernel(
    const float* __restrict__ W, __nv_bfloat16* __restrict__ hiT,
    __nv_bfloat16* __restrict__ loT, int K, int N)
{
    __shared__ float t[32][33];
    int nb = blockIdx.x * 32, kb = blockIdx.y * 32;
    int tx = threadIdx.x & 31, ty = threadIdx.x >> 5;
    #pragma unroll
    for (int i = 0; i < 32; i += 8)
        t[ty + i][tx] = W[(long long)(kb + ty + i) * N + nb + tx];
    __syncthreads();
    #pragma unroll
    for (int i = 0; i < 32; i += 8) {
        int r = ty + i;
        float v = t[tx][r];
        __nv_bfloat16 h = __float2bfloat16(v);
        __nv_bfloat16 l = __float2bfloat16(v - __bfloat162float(h));
        long long o = (long long)(nb + r) * K + kb + tx;
        hiT[o] = h; loT[o] = l;
    }
}

// ---------------------------------------------------------------------------
// mma.sync bf16 GEMM, hi/lo split (3 MMAs per k16).
// mode 0: fp32 + bias. mode 1: fp32 + bias + res. mode 2: GELU -> hi/lo split.
// mode 3: bias -> hi/lo split (QKV path).
// ---------------------------------------------------------------------------
__global__ __launch_bounds__(256, 1) void gemm_mma(
    const __nv_bfloat16* __restrict__ Ahi, const __nv_bfloat16* __restrict__ Alo,
    const __nv_bfloat16* __restrict__ Bhi, const __nv_bfloat16* __restrict__ Blo,
    const float* __restrict__ bias, const float* __restrict__ res,
    float* __restrict__ C, __nv_bfloat16* __restrict__ CHi,
    __nv_bfloat16* __restrict__ CLo, int N, int K, int mode)
{
    extern __shared__ __align__(1024) char smem[];
    uint32_t smemBase = smem_u32(smem);
    int tid = threadIdx.x, lane = tid & 31, wid = tid >> 5;
    int wm = wid >> 2, wn = wid & 3;
    long long rowBase = (long long)blockIdx.y * 128;
    long long colBase = (long long)blockIdx.x * 128;

    const __nv_bfloat16* a0g = Ahi + rowBase * K;
    const __nv_bfloat16* a1g = Alo + rowBase * K;
    const __nv_bfloat16* b0g = Bhi + colBase * K;
    const __nv_bfloat16* b1g = Blo + colBase * K;

    int ld_row = tid >> 2, ld_c16 = tid & 3;
    uint32_t off0 = swz((uint32_t)(ld_row * 64 + ld_c16 * 16));
    uint32_t off1 = swz((uint32_t)((ld_row + 64) * 64 + ld_c16 * 16));

    auto load_stage = [&](int stg, int kc) {
        uint32_t sb = smemBase + (uint32_t)stg * 32768u;
        long long g0 = (long long)ld_row * K + kc + ld_c16 * 8;
        long long g1 = (long long)(ld_row + 64) * K + kc + ld_c16 * 8;
        cpa16(sb + off0,          a0g + g0);
        cpa16(sb + off1,          a0g + g1);
        cpa16(sb + 8192 + off0,   a1g + g0);
        cpa16(sb + 8192 + off1,   a1g + g1);
        cpa16(sb + 16384 + off0,  b0g + g0);
        cpa16(sb + 16384 + off1,  b0g + g1);
        cpa16(sb + 24576 + off0,  b1g + g0);
        cpa16(sb + 24576 + off1,  b1g + g1);
        CP_COMMIT();
    };

    int NC = K >> 5;
    load_stage(0, 0);
    if (NC > 1) load_stage(1, 32);

    float acc[4][4][4] = {};
    int rl = lane & 15, cl = lane >> 4;

    for (int c = 0; c < NC; c++) {
        if (c + 1 < NC) { CP_WAIT1(); } else { CP_WAIT0(); }
        __syncthreads();
        uint32_t sb = smemBase + (uint32_t)(c % 3) * 32768u;
        #pragma unroll
        for (int hk = 0; hk < 2; hk++) {
            uint32_t ah[4][4], al[4][4], bh[2][4], bl[2][4];
            #pragma unroll
            for (int mt = 0; mt < 4; mt++) {
                uint32_t off = swz((uint32_t)((wm * 64 + mt * 16 + rl) * 64 + (hk * 2 + cl) * 16));
                LDSM4(ah[mt], sb + off);
                LDSM4(al[mt], sb + 8192 + off);
            }
            #pragma unroll
            for (int np = 0; np < 2; np++) {
                uint32_t off = swz((uint32_t)((wn * 32 + np * 16 + rl) * 64 + (hk * 2 + cl) * 16));
                LDSM4(bh[np], sb + 16384 + off);
                LDSM4(bl[np], sb + 24576 + off);
            }
            #pragma unroll
            for (int mt = 0; mt < 4; mt++)
                #pragma unroll
                for (int nt = 0; nt < 4; nt++) {
                    int np = nt >> 1, s = nt & 1;
                    MMA(acc[mt][nt], ah[mt], bh[np][s], bh[np][2 + s]);
                    MMA(acc[mt][nt], ah[mt], bl[np][s], bl[np][2 + s]);
                    MMA(acc[mt][nt], al[mt], bh[np][s], bh[np][2 + s]);
                }
        }
        __syncthreads();
        if (c + 2 < NC) load_stage((c + 2) % 3, (c + 2) * 32);
    }

    const float kk = 0.7071067811865475f;
    #pragma unroll
    for (int mt = 0; mt < 4; mt++) {
        #pragma unroll
        for (int nt = 0; nt < 4; nt++) {
            long long row = rowBase + wm * 64 + mt * 16 + (lane >> 2);
            long long col = colBase + wn * 32 + nt * 8 + (lane & 3) * 2;
            float bx = bias[col], by = bias[col + 1];
            #pragma unroll
            for (int hh = 0; hh < 2; hh++) {
                long long rr = row + hh * 8;
                float v0 = acc[mt][nt][hh * 2 + 0] + bx;
                float v1 = acc[mt][nt][hh * 2 + 1] + by;
                if (mode == 1) {
                    float2 r2 = *(const float2*)(res + rr * N + col);
                    v0 += r2.x; v1 += r2.y;
                    float2 o2; o2.x = v0; o2.y = v1;
                    *(float2*)(C + rr * N + col) = o2;
                } else if (mode == 2) {
                    v0 = 0.5f * v0 * (1.0f + erff(v0 * kk));
                    v1 = 0.5f * v1 * (1.0f + erff(v1 * kk));
                    *(uint32_t*)&CHi[rr * N + col] = pack_hi(v0, v1);
                    *(uint32_t*)&CLo[rr * N + col] = pack_lo(v0, v1);
                } else if (mode == 3) {
                    *(uint32_t*)&CHi[rr * N + col] = pack_hi(v0, v1);
                    *(uint32_t*)&CLo[rr * N + col] = pack_lo(v0, v1);
                } else {
                    float2 o2; o2.x = v0; o2.y = v1;
                    *(float2*)(C + rr * N + col) = o2;
                }
            }
        }
    }
}

// ---------------------------------------------------------------------------
// Tensor-core causal flash attention, hi/lo split (3-term everywhere).
// CTA: 128 q-rows x one head x one batch; 8 warps (m16 each); 64-key tiles
// double-buffered via cp.async. qkv given as bf16 hi/lo [4096][1536].
// Output written as bf16 hi/lo (direct input to W_o gemm).
// ---------------------------------------------------------------------------
__global__ __launch_bounds__(256, 1) void attn_mma(
    const __nv_bfloat16* __restrict__ gHi, const __nv_bfloat16* __restrict__ gLo,
    __nv_bfloat16* __restrict__ outHi, __nv_bfloat16* __restrict__ outLo)
{
    extern __shared__ __align__(1024) char smem[];
    uint32_t sb = smem_u32(smem);
    const uint32_t sQh = sb, sQl = sb + 16384;   // stages at sb+32768 + s*32768
    int tid = threadIdx.x, lane = tid & 31, w = tid >> 5;
    int qBlock = (int)gridDim.x - 1 - (int)blockIdx.x;    // big blocks first
    int qBase = qBlock * 128;
    int h = blockIdx.y, bb = blockIdx.z;
    long long rowOff = (long long)bb * Sq;

    // stage Q (cp.async group 0)
    #pragma unroll
    for (int i = 0; i < 4; i++) {
        int idx = i * 256 + tid;
        int r = idx >> 3, sg = idx & 7;
        long long g = (rowOff + qBase + r) * 1536 + h * 64 + sg * 8;
        uint32_t o = swz128((uint32_t)(r * 128 + sg * 16));
        cpa16(sQh + o, gHi + g);
        cpa16(sQl + o, gLo + g);
    }
    CP_COMMIT();

    int numT = qBase / 64 + 2;
    auto loadKV = [&](int s, int kb) {
        uint32_t base = sb + 32768u + (uint32_t)s * 32768u;
        #pragma unroll
        for (int i = 0; i < 2; i++) {
            int idx = i * 256 + tid;
            int r = idx >> 3, sg = idx & 7;
            uint32_t o = swz128((uint32_t)(r * 128 + sg * 16));
            long long gk = (rowOff + kb + r) * 1536 + 512 + h * 64 + sg * 8;
            cpa16(base + o,          gHi + gk);        // K hi
            cpa16(base + 8192 + o,   gLo + gk);        // K lo
            cpa16(base + 16384 + o,  gHi + gk + 512);  // V hi
            cpa16(base + 24576 + o,  gLo + gk + 512);  // V lo
        }
        CP_COMMIT();
    };
    loadKV(0, 0);
    if (numT > 1) loadKV(1, 64);

    if (numT > 1) { CP_WAIT1(); } else { CP_WAIT0(); }
    __syncthreads();

    int rl = lane & 15, cl = lane >> 4;
    uint32_t qh[4][4], ql[4][4];
    #pragma unroll
    for (int k16 = 0; k16 < 4; k16++) {
        uint32_t o = swz128((uint32_t)((w * 16 + rl) * 128 + (k16 * 2 + cl) * 16));
        LDSM4(qh[k16], sQh + o);
        LDSM4(ql[k16], sQl + o);
    }

    float oacc[8][4] = {};
    float m0 = -1e30f, m1 = -1e30f, l0 = 0.f, l1 = 0.f;
    int row0 = qBase + w * 16 + (lane >> 2);
    int row1 = row0 + 8;

    for (int t = 0; t < numT; t++) {
        if (t + 1 < numT) { CP_WAIT1(); } else { CP_WAIT0(); }
        __syncthreads();
        int kb = t * 64;
        if (kb <= qBase + w * 16 + 15) {
            uint32_t base = sb + 32768u + (uint32_t)(t & 1) * 32768u;
            // ---- S = Q K^T ----
            float sacc[8][4] = {};
            #pragma unroll
            for (int k16 = 0; k16 < 4; k16++) {
                uint32_t bKh[4][4], bKl[4][4];
                #pragma unroll
                for (int np = 0; np < 4; np++) {
                    uint32_t o = swz128((uint32_t)((np * 16 + rl) * 128 + (k16 * 2 + cl) * 16));
                    LDSM4(bKh[np], base + o);
                    LDSM4(bKl[np], base + 8192 + o);
                }
                #pragma unroll
                for (int nt = 0; nt < 8; nt++) {
                    int np = nt >> 1, s = nt & 1;
                    MMA(sacc[nt], qh[k16], bKh[np][s], bKh[np][2 + s]);
                    MMA(sacc[nt], qh[k16], bKl[np][s], bKl[np][2 + s]);
                    MMA(sacc[nt], ql[k16], bKh[np][s], bKh[np][2 + s]);
                }
            }
            // ---- softmax (online) ----
            float mx0 = -1e30f, mx1 = -1e30f;
            #pragma unroll
            for (int nt = 0; nt < 8; nt++) {
                #pragma unroll
                for (int j = 0; j < 4; j++) {
                    int col = kb + nt * 8 + (lane & 3) * 2 + (j & 1);
                    int rw = (j < 2) ? row0 : row1;
                    float v = sacc[nt][j] * 0.125f;
                    if (col > rw) v = -1e30f;
                    sacc[nt][j] = v;
                    if (j < 2) mx0 = fmaxf(mx0, v); else mx1 = fmaxf(mx1, v);
                }
            }
            mx0 = fmaxf(mx0, __shfl_xor_sync(0xffffffffu, mx0, 1));
            mx0 = fmaxf(mx0, __shfl_xor_sync(0xffffffffu, mx0, 2));
            mx1 = fmaxf(mx1, __shfl_xor_sync(0xffffffffu, mx1, 1));
            mx1 = fmaxf(mx1, __shfl_xor_sync(0xffffffffu, mx1, 2));
            float mn0 = fmaxf(m0, mx0), mn1 = fmaxf(m1, mx1);
            float c0 = __expf(m0 - mn0), c1 = __expf(m1 - mn1);
            m0 = mn0; m1 = mn1;
            l0 *= c0; l1 *= c1;
            #pragma unroll
            for (int nt = 0; nt < 8; nt++) {
                oacc[nt][0] *= c0; oacc[nt][1] *= c0;
                oacc[nt][2] *= c1; oacc[nt][3] *= c1;
            }
            #pragma unroll
            for (int nt = 0; nt < 8; nt++) {
                float p0 = __expf(sacc[nt][0] - m0);
                float p1 = __expf(sacc[nt][1] - m0);
                float p2 = __expf(sacc[nt][2] - m1);
                float p3 = __expf(sacc[nt][3] - m1);
                l0 += p0 + p1; l1 += p2 + p3;
                sacc[nt][0] = p0; sacc[nt][1] = p1; sacc[nt][2] = p2; sacc[nt][3] = p3;
            }
            // ---- O += P V ----
            int g = lane >> 3, lr = lane & 7;
            #pragma unroll
            for (int kp = 0; kp < 4; kp++) {
                int t0 = kp * 2, t1 = t0 + 1;
                uint32_t pah[4], pal[4];
                pah[0] = pack_hi(sacc[t0][0], sacc[t0][1]);
                pah[1] = pack_hi(sacc[t0][2], sacc[t0][3]);
                pah[2] = pack_hi(sacc[t1][0], sacc[t1][1]);
                pah[3] = pack_hi(sacc[t1][2], sacc[t1][3]);
                pal[0] = pack_lo(sacc[t0][0], sacc[t0][1]);
                pal[1] = pack_lo(sacc[t0][2], sacc[t0][3]);
                pal[2] = pack_lo(sacc[t1][0], sacc[t1][1]);
                pal[3] = pack_lo(sacc[t1][2], sacc[t1][3]);
                #pragma unroll
                for (int nd2 = 0; nd2 < 4; nd2++) {
                    uint32_t bVh[4], bVl[4];
                    uint32_t o = swz128((uint32_t)((kp * 16 + (g & 1) * 8 + lr) * 128
                                                   + nd2 * 32 + (g >> 1) * 16));
                    LDSM4T(bVh, base + 16384 + o);
                    LDSM4T(bVl, base + 24576 + o);
                    #pragma unroll
                    for (int u = 0; u < 2; u++) {
                        int nt = nd2 * 2 + u;
                        MMA(oacc[nt], pah, bVh[u * 2], bVh[u * 2 + 1]);
                        MMA(oacc[nt], pah, bVl[u * 2], bVl[u * 2 + 1]);
                        MMA(oacc[nt], pal, bVh[u * 2], bVh[u * 2 + 1]);
                    }
                }
            }
        }
        __syncthreads();
        if (t + 2 < numT) loadKV(t & 1, (t + 2) * 64);
    }

    l0 += __shfl_xor_sync(0xffffffffu, l0, 1);
    l0 += __shfl_xor_sync(0xffffffffu, l0, 2);
    l1 += __shfl_xor_sync(0xffffffffu, l1, 1);
    l1 += __shfl_xor_sync(0xffffffffu, l1, 2);
    float i0 = 1.0f / l0, i1 = 1.0f / l1;
    long long gr0 = (rowOff + row0) * (long long)Dm + h * 64 + (lane & 3) * 2;
    long long gr1 = (rowOff + row1) * (long long)Dm + h * 64 + (lane & 3) * 2;
    #pragma unroll
    for (int nt = 0; nt < 8; nt++) {
        float a0 = oacc[nt][0] * i0, a1 = oacc[nt][1] * i0;
        float a2 = oacc[nt][2] * i1, a3 = oacc[nt][3] * i1;
        *(uint32_t*)&outHi[gr0 + nt * 8] = pack_hi(a0, a1);
        *(uint32_t*)&outLo[gr0 + nt * 8] = pack_lo(a0, a1);
        *(uint32_t*)&outHi[gr1 + nt * 8] = pack_hi(a2, a3);
        *(uint32_t*)&outLo[gr1 + nt * 8] = pack_lo(a2, a3);
    }
}

// ---------------------------------------------------------------------------
extern "C" void kernel_launch(void* const* d_in, const int* in_sizes, int n_in,
                              void* d_out, int out_size)
{
    const int*   tokens  = (const int*)  d_in[0];
    const float* tok_emb = (const float*)d_in[1];
    const float* pe      = (const float*)d_in[2];
    const float* ln1_s   = (const float*)d_in[3];
    const float* ln1_b   = (const float*)d_in[4];
    const float* w_qkv   = (const float*)d_in[5];
    const float* b_qkv   = (const float*)d_in[6];
    const float* w_o     = (const float*)d_in[7];
    const float* b_o     = (const float*)d_in[8];
    const float* ln2_s   = (const float*)d_in[9];
    const float* ln2_b   = (const float*)d_in[10];
    const float* w1      = (const float*)d_in[11];
    const float* b1      = (const float*)d_in[12];
    const float* w2      = (const float*)d_in[13];
    const float* b2      = (const float*)d_in[14];
    const float* lnf_s   = (const float*)d_in[15];
    const float* lnf_b   = (const float*)d_in[16];
    const float* head_w  = (const float*)d_in[17];
    const float* head_b  = (const float*)d_in[18];
    float* out = (float*)d_out;

    float* x;
    __nv_bfloat16 *aHi, *aLo, *bHi, *bLo, *qkvTh, *qkvTl, *woTh, *woTl,
                  *w1Th, *w1Tl, *w2Th, *w2Tl, *hdTh, *hdTl;
    cudaGetSymbolAddress((void**)&x,    g_x);
    cudaGetSymbolAddress((void**)&aHi,  g_aHi);
    cudaGetSymbolAddress((void**)&aLo,  g_aLo);
    cudaGetSymbolAddress((void**)&bHi,  g_bHi);
    cudaGetSymbolAddress((void**)&bLo,  g_bLo);
    cudaGetSymbolAddress((void**)&qkvTh, g_qkvT_hi);
    cudaGetSymbolAddress((void**)&qkvTl, g_qkvT_lo);
    cudaGetSymbolAddress((void**)&woTh,  g_woT_hi);
    cudaGetSymbolAddress((void**)&woTl,  g_woT_lo);
    cudaGetSymbolAddress((void**)&w1Th,  g_w1T_hi);
    cudaGetSymbolAddress((void**)&w1Tl,  g_w1T_lo);
    cudaGetSymbolAddress((void**)&w2Th,  g_w2T_hi);
    cudaGetSymbolAddress((void**)&w2Tl,  g_w2T_lo);
    cudaGetSymbolAddress((void**)&hdTh,  g_hdT_hi);
    cudaGetSymbolAddress((void**)&hdTl,  g_hdT_lo);

    cudaFuncSetAttribute(gemm_mma, cudaFuncAttributeMaxDynamicSharedMemorySize, 98304);
    cudaFuncSetAttribute(attn_mma, cudaFuncAttributeMaxDynamicSharedMemorySize, 98304);
    const int SMEM = 98304;
    dim3 tb(256);

    embed_kernel<<<ROWS, 128>>>(tokens, tok_emb, pe, x);                               // 1
    wsplit_kernel<<<dim3(1536/32, 512/32), tb>>>(w_qkv, qkvTh, qkvTl, 512, 1536);      // 2
    ln_kernel<<<ROWS, 128>>>(x, ln1_s, ln1_b, aHi, aLo);                               // 3

    for (int l = 0; l < Lq; l++) {
        if (l > 0) {
            wsplit_kernel<<<dim3(1536/32, 512/32), tb>>>(w_qkv + (long long)l*512*1536, qkvTh + (long long)l*1536*512, qkvTl + (long long)l*1536*512, 512, 1536);
            ln_kernel<<<ROWS, 128>>>(x, ln1_s + l * Dm, ln1_b + l * Dm, aHi, aLo);
        }
        gemm_mma<<<dim3(1536/128, 32), 256, SMEM>>>(aHi, aLo,                          // #4 at l=0
            qkvTh + (long long)l*1536*512, qkvTl + (long long)l*1536*512,
            b_qkv + l*1536, nullptr, nullptr, bHi, bLo, 1536, 512, 3);
        attn_mma<<<dim3(Sq/128, Hh, Bq), 256, SMEM>>>(bHi, bLo, aHi, aLo);             // #5 at l=0
        wsplit_kernel<<<dim3(512/32, 512/32),  tb>>>(w_o + (long long)l*512*512,  woTh + (long long)l*512*512,  woTl + (long long)l*512*512,  512, 512);
        wsplit_kernel<<<dim3(2048/32, 512/32), tb>>>(w1  + (long long)l*512*2048, w1Th + (long long)l*2048*512, w1Tl + (long long)l*2048*512, 512, 2048);
        wsplit_kernel<<<dim3(512/32, 2048/32), tb>>>(w2  + (long long)l*2048*512, w2Th + (long long)l*512*2048, w2Tl + (long long)l*512*2048, 2048, 512);
        gemm_mma<<<dim3(512/128, 32), 256, SMEM>>>(aHi, aLo,
            woTh + (long long)l*512*512, woTl + (long long)l*512*512,
            b_o + l*512, x, x, nullptr, nullptr, 512, 512, 1);
        ln_kernel<<<ROWS, 128>>>(x, ln2_s + l * Dm, ln2_b + l * Dm, aHi, aLo);
        gemm_mma<<<dim3(2048/128, 32), 256, SMEM>>>(aHi, aLo,
            w1Th + (long long)l*2048*512, w1Tl + (long long)l*2048*512,
            b1 + l*2048, nullptr, nullptr, bHi, bLo, 2048, 512, 2);
        gemm_mma<<<dim3(512/128, 32), 256, SMEM>>>(bHi, bLo,
            w2Th + (long long)l*512*2048, w2Tl + (long long)l*512*2048,
            b2 + l*512, x, x, nullptr, nullptr, 512, 2048, 1);
    }
    wsplit_kernel<<<dim3(32000/32, 512/32), tb>>>(head_w, hdTh, hdTl, 512, 32000);
    ln_kernel<<<ROWS, 128>>>(x, lnf_s, lnf_b, aHi, aLo);
    gemm_mma<<<dim3(32000/128, 32), 256, SMEM>>>(aHi, aLo, hdTh, hdTl,
        head_b, nullptr, out, nullptr, nullptr, 32000, 512, 0);
}